// round 1
// baseline (speedup 1.0000x reference)
#include <cuda_runtime.h>

#define BB 32
#define TT 4096
#define DX 128
#define HH 128
#define GG 384       // 3*H
#define NK 10
#define NROWS (BB*TT)   // 131072

// Scratch: input projections [t*B+b][768] (fwd gates 0..383, bwd 384..767)
__device__ float g_xp[(size_t)NROWS * 768];
// Hidden states concatenated [b*T+t][256] (fwd 0..127, bwd 128..255)
__device__ float g_h[(size_t)NROWS * 256];

// Packed dual fp32 FMA (sm_103a): d.lo += a.lo*b.lo ; d.hi += a.hi*b.hi
#define FFMA2(acc, aa, bb) \
    asm("fma.rn.f32x2 %0, %1, %2, %0;" : "+l"(acc) : "l"(aa), "l"(bb))

__device__ __forceinline__ float sum_acc(unsigned long long a0, unsigned long long a1) {
    return __uint_as_float((unsigned)a0) + __uint_as_float((unsigned)(a0 >> 32))
         + __uint_as_float((unsigned)a1) + __uint_as_float((unsigned)(a1 >> 32));
}

// ---------------------------------------------------------------------------
// Kernel 1: input projections xp = x @ W_ih^T + b_ih for both directions.
// One CTA = 384 threads = 384 gate columns of one direction; each thread keeps
// its 128 weights in registers (64 packed u64). CTA streams rows (t,b).
// ---------------------------------------------------------------------------
__global__ __launch_bounds__(384, 1) void proj_kernel(
    const float* __restrict__ x,
    const float* __restrict__ Wf, const float* __restrict__ bf,
    const float* __restrict__ Wb, const float* __restrict__ bb)
{
    const int d = blockIdx.x / 74;   // 0 fwd, 1 bwd   (grid = 148)
    const int c = blockIdx.x % 74;
    const float* W  = d ? Wb : Wf;
    const float* bi = d ? bb : bf;
    const int j = threadIdx.x;

    unsigned long long w[64];
    const unsigned long long* wrow = (const unsigned long long*)(W + j * DX);
#pragma unroll
    for (int i = 0; i < 64; ++i) w[i] = wrow[i];
    const float bias = bi[j];

    __shared__ __align__(16) float xs[2][DX];

    const int chunk = (NROWS + 73) / 74;      // 1772
    const int r0 = c * chunk;
    const int r1 = min(r0 + chunk, NROWS);

    // prefetch first row (row r -> b = r&31, t = r>>5 ; x is [B,T,Dx])
    float xr = 0.f;
    if (j < DX) {
        int b0 = r0 & 31, t0 = r0 >> 5;
        xr = x[((size_t)(b0 * TT + t0)) * DX + j];
    }
    int p = 0;
    for (int r = r0; r < r1; ++r) {
        if (j < DX) {
            xs[p][j] = xr;
            if (r + 1 < r1) {
                int bn = (r + 1) & 31, tn = (r + 1) >> 5;
                xr = x[((size_t)(bn * TT + tn)) * DX + j];
            }
        }
        __syncthreads();
        unsigned long long a0 = 0ull, a1 = 0ull;
        const ulonglong2* hs = (const ulonglong2*)xs[p];
#pragma unroll
        for (int i = 0; i < 32; ++i) {
            ulonglong2 hv = hs[i];           // LDS.128 broadcast
            FFMA2(a0, hv.x, w[2 * i]);
            FFMA2(a1, hv.y, w[2 * i + 1]);
        }
        g_xp[(size_t)r * 768 + d * GG + j] = sum_acc(a0, a1) + bias;
        p ^= 1;   // double buffer: safe, writes to buf p' happen pre-barrier,
                  // reads of buf p post-barrier (see analysis)
    }
}

// ---------------------------------------------------------------------------
// Kernel 2: the sequential GRU scan. One CTA per (direction, batch) sequence:
// 64 CTAs. Thread j owns recurrent weight row j (registers). Per step:
//   dot over h (SMEM broadcast, FFMA2) -> gate pre-acts -> barrier ->
//   threads 0..127 apply nonlinearities, update h, store to g_h -> barrier.
// ---------------------------------------------------------------------------
__global__ __launch_bounds__(384, 1) void scan_kernel(
    const float* __restrict__ Whf, const float* __restrict__ bhf,
    const float* __restrict__ Whb, const float* __restrict__ bhb)
{
    const int bx = blockIdx.x;          // 64
    const int d = bx >> 5;
    const int b = bx & 31;
    const float* W  = d ? Whb : Whf;
    const float* bh = d ? bhb : bhf;
    const int j = threadIdx.x;

    unsigned long long w[64];
    const unsigned long long* wrow = (const unsigned long long*)(W + j * HH);
#pragma unroll
    for (int i = 0; i < 64; ++i) w[i] = wrow[i];
    const float bias = bh[j];

    __shared__ __align__(16) float h_sh[HH];
    __shared__ float ga[GG];
    __shared__ float xn_sh[HH];

    if (j < HH) h_sh[j] = 0.f;
    __syncthreads();

    const int stride = BB * 768;                       // floats per timestep
    const int t0 = d ? (TT - 1) : 0;
    const float* xptr = g_xp + (size_t)(t0 * BB + b) * 768 + d * GG + j;
    const int dstep = d ? -stride : stride;

    float xv = __ldg(xptr);                            // prefetch t0
    float* hout = g_h + (size_t)(b * TT) * 256 + d * HH + j;  // used when j<128

    for (int tt = 0; tt < TT; ++tt) {
        const float xg = xv;
        if (tt + 1 < TT) xv = __ldg(xptr + dstep);     // prefetch next step
        xptr += dstep;

        unsigned long long a0 = 0ull, a1 = 0ull;
        const ulonglong2* hs = (const ulonglong2*)h_sh;
#pragma unroll
        for (int i = 0; i < 32; ++i) {
            ulonglong2 hv = hs[i];                     // LDS.128 broadcast
            FFMA2(a0, hv.x, w[2 * i]);
            FFMA2(a1, hv.y, w[2 * i + 1]);
        }
        const float hp = sum_acc(a0, a1) + bias;       // h@Whh^T + bhh
        if (j < 2 * HH) {
            ga[j] = xg + hp;                           // r,z pre-activations
        } else {
            ga[j] = hp;                                // hn kept separate
            xn_sh[j - 2 * HH] = xg;                    // xn stashed
        }
        __syncthreads();

        if (j < HH) {
            const float r = 1.f / (1.f + __expf(-ga[j]));
            const float z = 1.f / (1.f + __expf(-ga[HH + j]));
            const float npre = xn_sh[j] + r * ga[2 * HH + j];
            const float e = __expf(2.f * npre);        // tanh = 1 - 2/(e+1)
            const float n = 1.f - __fdividef(2.f, e + 1.f);
            const float hnew = n + z * (h_sh[j] - n);  // (1-z)n + z h
            h_sh[j] = hnew;
            const int tcur = d ? (TT - 1 - tt) : tt;
            hout[(size_t)tcur * 256] = hnew;
        }
        __syncthreads();
    }
}

// ---------------------------------------------------------------------------
// Kernel 3: FC head out = hcat @ Wfc^T + bfc. Warp per row, lane-strided
// loads (coalesced), shfl reduction. Memory-bound (~134 MB).
// ---------------------------------------------------------------------------
__global__ __launch_bounds__(256) void fc_kernel(
    const float* __restrict__ Wfc, const float* __restrict__ bfc,
    float* __restrict__ out)
{
    __shared__ float Ws[NK * 256];
    __shared__ float bs[NK];
    for (int i = threadIdx.x; i < NK * 256; i += 256) Ws[i] = Wfc[i];
    if (threadIdx.x < NK) bs[threadIdx.x] = bfc[threadIdx.x];
    __syncthreads();

    const int gwarp = (blockIdx.x * 256 + threadIdx.x) >> 5;
    const int lane = threadIdx.x & 31;
    const int nwarps = gridDim.x * 8;

    for (int row = gwarp; row < NROWS; row += nwarps) {
        const float* hr = g_h + (size_t)row * 256;
        float hv[8];
#pragma unroll
        for (int m = 0; m < 8; ++m) hv[m] = hr[lane + 32 * m];
        float acc[NK];
#pragma unroll
        for (int k = 0; k < NK; ++k) {
            float s = 0.f;
#pragma unroll
            for (int m = 0; m < 8; ++m) s += hv[m] * Ws[k * 256 + lane + 32 * m];
            acc[k] = s;
        }
#pragma unroll
        for (int k = 0; k < NK; ++k) {
#pragma unroll
            for (int o = 16; o > 0; o >>= 1)
                acc[k] += __shfl_down_sync(0xffffffffu, acc[k], o);
        }
        if (lane == 0) {
#pragma unroll
            for (int k = 0; k < NK; ++k)
                out[(size_t)row * NK + k] = acc[k] + bs[k];
        }
    }
}

// ---------------------------------------------------------------------------
extern "C" void kernel_launch(void* const* d_in, const int* in_sizes, int n_in,
                              void* d_out, int out_size)
{
    const float* x    = (const float*)d_in[0];
    const float* Wihf = (const float*)d_in[1];
    const float* Whhf = (const float*)d_in[2];
    const float* bihf = (const float*)d_in[3];
    const float* bhhf = (const float*)d_in[4];
    const float* Wihb = (const float*)d_in[5];
    const float* Whhb = (const float*)d_in[6];
    const float* bihb = (const float*)d_in[7];
    const float* bhhb = (const float*)d_in[8];
    const float* Wfc  = (const float*)d_in[9];
    const float* bfc  = (const float*)d_in[10];
    float* out = (float*)d_out;

    proj_kernel<<<148, 384>>>(x, Wihf, bihf, Wihb, bihb);
    scan_kernel<<<64, 384>>>(Whhf, bhhf, Whhb, bhhb);
    fc_kernel<<<296, 256>>>(Wfc, bfc, out);
}